// round 2
// baseline (speedup 1.0000x reference)
#include <cuda_runtime.h>
#include <math.h>

#define Bn 4
#define Sn 2048
#define En 1024
#define Hn 16
#define Dn 64
#define Mn (Bn*Sn)          // 8192

// ---------------------------------------------------------------------------
// Scratch buffers (device globals; allocation is forbidden)
// ---------------------------------------------------------------------------
__device__ __align__(16) float g_q[(size_t)Mn*En];     // [H][S][B][D]
__device__ __align__(16) float g_k[(size_t)Mn*En];     // [H][S][B][D]
__device__ __align__(16) float g_v[(size_t)Mn*En];     // [H][S][B][D]
__device__ __align__(16) float g_gate[(size_t)Mn*En];  // [B*S][E] gate preact -> fused buffer
__device__ __align__(16) float g_o1[(size_t)Mn*En];    // [B*S][E] scan output (q + z)

// ---------------------------------------------------------------------------
// NT GEMM: C[m][n] = sum_k A[m][k] * Bw[n][k], M=8192, N=1024, K=1024
// MODE 0: scatter to [H][S][B][D];  MODE 1: flat [m][n]
// 128x128 tile, 256 threads, 8x8 per thread, BK=8, double buffered.
// ---------------------------------------------------------------------------
template<int MODE>
__global__ void __launch_bounds__(256, 2) gemm_nt(const float* __restrict__ A,
                                                  const float* __restrict__ Bw,
                                                  float* __restrict__ C)
{
    __shared__ __align__(16) float As[2][8][132];
    __shared__ __align__(16) float Bs[2][8][132];

    const int t = threadIdx.x;
    const int bm = blockIdx.y;
    const int bn = blockIdx.x;
    const int arow = t >> 1;
    const int ak   = (t & 1) * 4;
    const int tx = t & 15;
    const int ty = t >> 4;

    const float* Ag = A  + (size_t)(bm*128 + arow)*1024 + ak;
    const float* Bg = Bw + (size_t)(bn*128 + arow)*1024 + ak;

    float acc[8][8];
#pragma unroll
    for (int i = 0; i < 8; i++)
#pragma unroll
        for (int j = 0; j < 8; j++) acc[i][j] = 0.0f;

    // preload tile 0
    {
        float4 av = *(const float4*)Ag;
        float4 bv = *(const float4*)Bg;
        As[0][ak+0][arow] = av.x; As[0][ak+1][arow] = av.y;
        As[0][ak+2][arow] = av.z; As[0][ak+3][arow] = av.w;
        Bs[0][ak+0][arow] = bv.x; Bs[0][ak+1][arow] = bv.y;
        Bs[0][ak+2][arow] = bv.z; Bs[0][ak+3][arow] = bv.w;
    }
    __syncthreads();

#pragma unroll 1
    for (int kt = 0; kt < 128; kt++) {
        const int buf = kt & 1;
        float4 av2, bv2;
        const bool more = (kt + 1 < 128);
        if (more) {
            av2 = *(const float4*)(Ag + (kt+1)*8);
            bv2 = *(const float4*)(Bg + (kt+1)*8);
        }
#pragma unroll
        for (int kk = 0; kk < 8; kk++) {
            float a[8], bb[8];
            *(float4*)&a[0]  = *(const float4*)&As[buf][kk][ty*4];
            *(float4*)&a[4]  = *(const float4*)&As[buf][kk][64 + ty*4];
            *(float4*)&bb[0] = *(const float4*)&Bs[buf][kk][tx*4];
            *(float4*)&bb[4] = *(const float4*)&Bs[buf][kk][64 + tx*4];
#pragma unroll
            for (int i = 0; i < 8; i++)
#pragma unroll
                for (int j = 0; j < 8; j++)
                    acc[i][j] += a[i] * bb[j];
        }
        if (more) {
            const int nb = buf ^ 1;
            As[nb][ak+0][arow] = av2.x; As[nb][ak+1][arow] = av2.y;
            As[nb][ak+2][arow] = av2.z; As[nb][ak+3][arow] = av2.w;
            Bs[nb][ak+0][arow] = bv2.x; Bs[nb][ak+1][arow] = bv2.y;
            Bs[nb][ak+2][arow] = bv2.z; Bs[nb][ak+3][arow] = bv2.w;
            __syncthreads();
        }
    }

    // epilogue
#pragma unroll
    for (int i = 0; i < 8; i++) {
        const int r = (i < 4) ? (ty*4 + i) : (64 + ty*4 + (i - 4));
        const int m = bm*128 + r;
#pragma unroll
        for (int jg = 0; jg < 2; jg++) {
            const int c = bn*128 + (jg ? (64 + tx*4) : (tx*4));
            float4 vv = make_float4(acc[i][jg*4+0], acc[i][jg*4+1],
                                    acc[i][jg*4+2], acc[i][jg*4+3]);
            if (MODE == 0) {
                const int bb_ = m >> 11;        // batch
                const int sI  = m & 2047;       // token
                const int hh  = c >> 6;
                const int d   = c & 63;
                *(float4*)&C[(((size_t)hh*Sn + sI)*Bn + bb_)*Dn + d] = vv;
            } else {
                *(float4*)&C[(size_t)m*En + c] = vv;
            }
        }
    }
}

// ---------------------------------------------------------------------------
// Reduction over the 64 threads sharing a batch row b (2 warps): shfl within
// warp + smem exchange across the warp pair. Double-buffered redbuf.
// ---------------------------------------------------------------------------
template<int NV>
__device__ __forceinline__ void red64(float* v, float* redbuf, int w, int b)
{
#pragma unroll
    for (int off = 16; off > 0; off >>= 1)
#pragma unroll
        for (int i = 0; i < NV; i++)
            v[i] += __shfl_xor_sync(0xffffffffu, v[i], off);
    if ((threadIdx.x & 31) == 0) {
#pragma unroll
        for (int i = 0; i < NV; i++) redbuf[w*8 + i] = v[i];
    }
    __syncthreads();
#pragma unroll
    for (int i = 0; i < NV; i++)
        v[i] = redbuf[(2*b)*8 + i] + redbuf[(2*b+1)*8 + i];
}

// ---------------------------------------------------------------------------
// TTT scan: one CTA per head, 256 threads. Thread t = (b = t>>6, e = t&63).
// W[64][64] register-resident: thread holds W[b*16 + i][e], i in 0..15.
// Per token: 1 full forward (h0 = kW + b), rank-4 corrections for the two
// SGD steps (h' = h - LR*(G dh + db)), one fused W update.
// ---------------------------------------------------------------------------
__global__ void __launch_bounds__(256, 1) scan_kernel(
    const float* __restrict__ fw_W, const float* __restrict__ fw_b,
    const float* __restrict__ fw_g, const float* __restrict__ fw_bl,
    const float* __restrict__ ttt_g, const float* __restrict__ ttt_b)
{
    const int h = blockIdx.x;
    const int t = threadIdx.x;
    const int b = t >> 6;
    const int e = t & 63;
    const int w = t >> 5;

    __shared__ __align__(16) float k_s[256];
    __shared__ float part_s[1024];
    __shared__ float dh_s[256];
    __shared__ float dpv_s[256];
    __shared__ float dph_s[256];
    __shared__ float dhsum_s[256];
    __shared__ float red_s[2][64];

    float Wr[16];
    {
        const float* W0 = fw_W + ((size_t)h*Dn + b*16)*Dn + e;
#pragma unroll
        for (int i = 0; i < 16; i++) Wr[i] = W0[(size_t)i*Dn];
    }
    float bp   = fw_b[h*Dn + e];
    float gpar = fw_g[h*Dn + e];
    float blp  = fw_bl[h*Dn + e];
    const float tg = ttt_g[h*Dn + e];
    const float tb = ttt_b[h*Dn + e];

    const float* qh = g_q + (size_t)h*Sn*(Bn*Dn);
    const float* kh = g_k + (size_t)h*Sn*(Bn*Dn);
    const float* vh = g_v + (size_t)h*Sn*(Bn*Dn);

    float kp = kh[t], vp = vh[t], qp = qh[t];

    const float LR  = 0.1f;
    const float EPS = 1e-5f;
    const float C0  = 2.0f / 4096.0f;   // 2 / (B*H*D)
    const float IN  = 1.0f / 64.0f;

    for (int s = 0; s < Sn; s++) {
        __syncthreads();                       // protect k_s/dhsum_s readers
        const float k_r = kp, v_r = vp, q_r = qp;
        k_s[t] = k_r;
        if (s + 1 < Sn) {                      // prefetch next token
            kp = kh[(s+1)*256 + t];
            vp = vh[(s+1)*256 + t];
            qp = qh[(s+1)*256 + t];
        }
        __syncthreads();

        // ---- forward partials: this thread acts as dgrp = b over d-slice
        float p0 = 0.f, p1 = 0.f, p2 = 0.f, p3 = 0.f;
#pragma unroll
        for (int j = 0; j < 4; j++) {
            float4 k0 = *(const float4*)&k_s[0*64 + b*16 + 4*j];
            float4 k1 = *(const float4*)&k_s[1*64 + b*16 + 4*j];
            float4 k2 = *(const float4*)&k_s[2*64 + b*16 + 4*j];
            float4 k3 = *(const float4*)&k_s[3*64 + b*16 + 4*j];
            float w0 = Wr[4*j], w1 = Wr[4*j+1], w2 = Wr[4*j+2], w3 = Wr[4*j+3];
            p0 += k0.x*w0 + k0.y*w1 + k0.z*w2 + k0.w*w3;
            p1 += k1.x*w0 + k1.y*w1 + k1.z*w2 + k1.w*w3;
            p2 += k2.x*w0 + k2.y*w1 + k2.z*w2 + k2.w*w3;
            p3 += k3.x*w0 + k3.y*w1 + k3.z*w2 + k3.w*w3;
        }
        part_s[(0*4 + b)*64 + e] = p0;
        part_s[(1*4 + b)*64 + e] = p1;
        part_s[(2*4 + b)*64 + e] = p2;
        part_s[(3*4 + b)*64 + e] = p3;

        float r1[6];
        r1[2] = k_r * k_s[0*64 + e];   // Gram partials G[b][b']
        r1[3] = k_r * k_s[1*64 + e];
        r1[4] = k_r * k_s[2*64 + e];
        r1[5] = k_r * k_s[3*64 + e];
        __syncthreads();

        float h0 = part_s[(b*4+0)*64 + e] + part_s[(b*4+1)*64 + e]
                 + part_s[(b*4+2)*64 + e] + part_s[(b*4+3)*64 + e] + bp;
        r1[0] = h0; r1[1] = h0*h0;
        red64<6>(r1, red_s[0], w, b);
        const float mu0 = r1[0]*IN;
        const float rs0 = rsqrtf(r1[1]*IN - mu0*mu0 + EPS);
        const float G0 = r1[2], G1 = r1[3], G2 = r1[4], G3 = r1[5];
        const float hat0 = (h0 - mu0)*rs0;
        const float tgt = v_r - k_r;

        // ---- SGD step 1
        const float dp0   = C0*(hat0*gpar + blp - tgt);
        const float dhat0 = dp0*gpar;
        float r2[2] = {dhat0, dhat0*hat0};
        red64<2>(r2, red_s[1], w, b);
        const float dh0 = rs0*(dhat0 - r2[0]*IN - hat0*(r2[1]*IN));
        dh_s[t] = dh0; dpv_s[t] = dp0; dph_s[t] = dp0*hat0;
        __syncthreads();
        const float d0 = dh_s[0*64+e], d1 = dh_s[1*64+e],
                    d2 = dh_s[2*64+e], d3 = dh_s[3*64+e];
        const float sdh  = d0 + d1 + d2 + d3;
        const float sdp  = dpv_s[0*64+e]+dpv_s[1*64+e]+dpv_s[2*64+e]+dpv_s[3*64+e];
        const float sdph = dph_s[0*64+e]+dph_s[1*64+e]+dph_s[2*64+e]+dph_s[3*64+e];
        const float g1  = gpar - LR*sdph;
        const float bl1 = blp  - LR*sdp;
        const float b1  = bp   - LR*sdh;
        const float h1  = h0 - LR*(G0*d0 + G1*d1 + G2*d2 + G3*d3 + sdh);

        // ---- SGD step 2
        float r3[2] = {h1, h1*h1};
        red64<2>(r3, red_s[0], w, b);
        const float mu1 = r3[0]*IN;
        const float rs1 = rsqrtf(r3[1]*IN - mu1*mu1 + EPS);
        const float hat1  = (h1 - mu1)*rs1;
        const float dp1   = C0*(hat1*g1 + bl1 - tgt);
        const float dhat1 = dp1*g1;
        float r4[2] = {dhat1, dhat1*hat1};
        red64<2>(r4, red_s[1], w, b);
        const float dh1 = rs1*(dhat1 - r4[0]*IN - hat1*(r4[1]*IN));
        dh_s[t] = dh1; dpv_s[t] = dp1; dph_s[t] = dp1*hat1; dhsum_s[t] = dh0 + dh1;
        __syncthreads();
        const float e0 = dh_s[0*64+e], e1 = dh_s[1*64+e],
                    e2 = dh_s[2*64+e], e3 = dh_s[3*64+e];
        const float sdh1  = e0 + e1 + e2 + e3;
        const float sdp1  = dpv_s[0*64+e]+dpv_s[1*64+e]+dpv_s[2*64+e]+dpv_s[3*64+e];
        const float sdph1 = dph_s[0*64+e]+dph_s[1*64+e]+dph_s[2*64+e]+dph_s[3*64+e];
        const float g2  = g1  - LR*sdph1;
        const float bl2 = bl1 - LR*sdp1;
        const float b2  = b1  - LR*sdh1;
        const float h2  = h1 - LR*(G0*e0 + G1*e1 + G2*e2 + G3*e3 + sdh1);

        // ---- final forward + ttt_norm
        float r5[2] = {h2, h2*h2};
        red64<2>(r5, red_s[0], w, b);
        const float mu2 = r5[0]*IN;
        const float rs2 = rsqrtf(r5[1]*IN - mu2*mu2 + EPS);
        const float z = (h2 - mu2)*rs2*g2 + bl2;
        float r6[2] = {z, z*z};
        red64<2>(r6, red_s[1], w, b);
        const float muz = r6[0]*IN;
        const float rsz = rsqrtf(r6[1]*IN - muz*muz + EPS);
        const float zn = (z - muz)*rsz*tg + tb;

        g_o1[((size_t)(b*Sn + s))*En + h*Dn + e] = q_r + zn;

        gpar = g2; blp = bl2; bp = b2;

        // ---- fused W update: W -= LR * k^T (dh0 + dh1)
        const float cb0 = LR * dhsum_s[0*64 + e];
        const float cb1 = LR * dhsum_s[1*64 + e];
        const float cb2 = LR * dhsum_s[2*64 + e];
        const float cb3 = LR * dhsum_s[3*64 + e];
#pragma unroll
        for (int j = 0; j < 4; j++) {
            float4 k0 = *(const float4*)&k_s[0*64 + b*16 + 4*j];
            float4 k1 = *(const float4*)&k_s[1*64 + b*16 + 4*j];
            float4 k2 = *(const float4*)&k_s[2*64 + b*16 + 4*j];
            float4 k3 = *(const float4*)&k_s[3*64 + b*16 + 4*j];
            Wr[4*j+0] -= k0.x*cb0 + k1.x*cb1 + k2.x*cb2 + k3.x*cb3;
            Wr[4*j+1] -= k0.y*cb0 + k1.y*cb1 + k2.y*cb2 + k3.y*cb3;
            Wr[4*j+2] -= k0.z*cb0 + k1.z*cb1 + k2.z*cb2 + k3.z*cb3;
            Wr[4*j+3] -= k0.w*cb0 + k1.w*cb1 + k2.w*cb2 + k3.w*cb3;
        }
    }
}

// ---------------------------------------------------------------------------
// Fused post-LayerNorm * gelu(gate): one CTA per row (B*S rows), in-place
// into g_gate so the final GEMM reads one buffer.
// ---------------------------------------------------------------------------
__global__ void __launch_bounds__(256, 1) postgate_kernel(
    const float* __restrict__ pg, const float* __restrict__ pb)
{
    const int row = blockIdx.x;
    const int t = threadIdx.x;
    const int w = t >> 5, lane = t & 31;
    const float* xr = g_o1 + (size_t)row*En;

    float v[4];
    float s = 0.f, ss = 0.f;
#pragma unroll
    for (int j = 0; j < 4; j++) {
        float x = xr[t + 256*j];
        v[j] = x; s += x; ss += x*x;
    }
#pragma unroll
    for (int off = 16; off > 0; off >>= 1) {
        s  += __shfl_xor_sync(0xffffffffu, s, off);
        ss += __shfl_xor_sync(0xffffffffu, ss, off);
    }
    __shared__ float rsm[16];
    if (lane == 0) { rsm[w] = s; rsm[8 + w] = ss; }
    __syncthreads();
    float S = 0.f, SS = 0.f;
#pragma unroll
    for (int i = 0; i < 8; i++) { S += rsm[i]; SS += rsm[8 + i]; }
    const float mu = S * (1.0f/1024.0f);
    const float r  = rsqrtf(SS * (1.0f/1024.0f) - mu*mu + 1e-5f);

    float* gr = g_gate + (size_t)row*En;
#pragma unroll
    for (int j = 0; j < 4; j++) {
        const int e_ = t + 256*j;
        const float y  = (v[j] - mu)*r*pg[e_] + pb[e_];
        const float xg = gr[e_];
        const float gl = 0.5f*xg*(1.0f + tanhf(0.7978845608028654f*
                                 (xg + 0.044715f*xg*xg*xg)));
        gr[e_] = y * gl;
    }
}

// ---------------------------------------------------------------------------
extern "C" void kernel_launch(void* const* d_in, const int* in_sizes, int n_in,
                              void* d_out, int out_size)
{
    const float* x    = (const float*)d_in[0];
    const float* Wq   = (const float*)d_in[1];
    const float* Wk   = (const float*)d_in[2];
    const float* Wv   = (const float*)d_in[3];
    const float* Wo   = (const float*)d_in[4];
    const float* Wg   = (const float*)d_in[5];
    const float* fwW  = (const float*)d_in[6];
    const float* fwb  = (const float*)d_in[7];
    const float* fwg  = (const float*)d_in[8];
    const float* fwbl = (const float*)d_in[9];
    const float* tttg = (const float*)d_in[10];
    const float* tttb = (const float*)d_in[11];
    const float* pg   = (const float*)d_in[12];
    const float* pb   = (const float*)d_in[13];
    float* out = (float*)d_out;

    float *pq, *pk, *pv, *pgt;
    cudaGetSymbolAddress((void**)&pq,  g_q);
    cudaGetSymbolAddress((void**)&pk,  g_k);
    cudaGetSymbolAddress((void**)&pv,  g_v);
    cudaGetSymbolAddress((void**)&pgt, g_gate);

    dim3 grid(En/128, Mn/128), blk(256);
    gemm_nt<0><<<grid, blk>>>(x, Wq, pq);
    gemm_nt<0><<<grid, blk>>>(x, Wk, pk);
    gemm_nt<0><<<grid, blk>>>(x, Wv, pv);
    gemm_nt<1><<<grid, blk>>>(x, Wg, pgt);
    scan_kernel<<<Hn, 256>>>(fwW, fwb, fwg, fwbl, tttg, tttb);
    postgate_kernel<<<Mn, 256>>>(pg, pb);
    gemm_nt<1><<<grid, blk>>>(pgt, Wo, out);
}

// round 3
// speedup vs baseline: 1.1836x; 1.1836x over previous
#include <cuda_runtime.h>
#include <math.h>

#define Bn 4
#define Sn 2048
#define En 1024
#define Hn 16
#define Dn 64
#define Mn (Bn*Sn)          // 8192

// ---------------------------------------------------------------------------
// Scratch buffers (device globals; allocation is forbidden)
// ---------------------------------------------------------------------------
__device__ __align__(16) float g_q[(size_t)Mn*En];     // [H][S][B][D]
__device__ __align__(16) float g_k[(size_t)Mn*En];     // [H][S][B][D]
__device__ __align__(16) float g_v[(size_t)Mn*En];     // [H][S][B][D]
__device__ __align__(16) float g_gate[(size_t)Mn*En];  // [B*S][E]
__device__ __align__(16) float g_o1[(size_t)Mn*En];    // [B*S][E]

// ---------------------------------------------------------------------------
// NT GEMM body: C[m][n] = sum_k A[m][k]*Bw[n][k]; 128x128 tile, 256 thr, 8x8.
// MODE 0: scatter to [H][S][B][D];  MODE 1: flat.
// ---------------------------------------------------------------------------
template<int MODE>
__device__ __forceinline__ void gemm_body(const float* __restrict__ A,
                                          const float* __restrict__ Bw,
                                          float* __restrict__ C,
                                          int bm, int bn)
{
    __shared__ __align__(16) float As[2][8][132];
    __shared__ __align__(16) float Bs[2][8][132];

    const int t = threadIdx.x;
    const int arow = t >> 1;
    const int ak   = (t & 1) * 4;
    const int tx = t & 15;
    const int ty = t >> 4;

    const float* Ag = A  + (size_t)(bm*128 + arow)*1024 + ak;
    const float* Bg = Bw + (size_t)(bn*128 + arow)*1024 + ak;

    float acc[8][8];
#pragma unroll
    for (int i = 0; i < 8; i++)
#pragma unroll
        for (int j = 0; j < 8; j++) acc[i][j] = 0.0f;

    {
        float4 av = *(const float4*)Ag;
        float4 bv = *(const float4*)Bg;
        As[0][ak+0][arow] = av.x; As[0][ak+1][arow] = av.y;
        As[0][ak+2][arow] = av.z; As[0][ak+3][arow] = av.w;
        Bs[0][ak+0][arow] = bv.x; Bs[0][ak+1][arow] = bv.y;
        Bs[0][ak+2][arow] = bv.z; Bs[0][ak+3][arow] = bv.w;
    }
    __syncthreads();

#pragma unroll 1
    for (int kt = 0; kt < 128; kt++) {
        const int buf = kt & 1;
        float4 av2, bv2;
        const bool more = (kt + 1 < 128);
        if (more) {
            av2 = *(const float4*)(Ag + (kt+1)*8);
            bv2 = *(const float4*)(Bg + (kt+1)*8);
        }
#pragma unroll
        for (int kk = 0; kk < 8; kk++) {
            float a[8], bb[8];
            *(float4*)&a[0]  = *(const float4*)&As[buf][kk][ty*4];
            *(float4*)&a[4]  = *(const float4*)&As[buf][kk][64 + ty*4];
            *(float4*)&bb[0] = *(const float4*)&Bs[buf][kk][tx*4];
            *(float4*)&bb[4] = *(const float4*)&Bs[buf][kk][64 + tx*4];
#pragma unroll
            for (int i = 0; i < 8; i++)
#pragma unroll
                for (int j = 0; j < 8; j++)
                    acc[i][j] += a[i] * bb[j];
        }
        if (more) {
            const int nb = buf ^ 1;
            As[nb][ak+0][arow] = av2.x; As[nb][ak+1][arow] = av2.y;
            As[nb][ak+2][arow] = av2.z; As[nb][ak+3][arow] = av2.w;
            Bs[nb][ak+0][arow] = bv2.x; Bs[nb][ak+1][arow] = bv2.y;
            Bs[nb][ak+2][arow] = bv2.z; Bs[nb][ak+3][arow] = bv2.w;
            __syncthreads();
        }
    }

#pragma unroll
    for (int i = 0; i < 8; i++) {
        const int r = (i < 4) ? (ty*4 + i) : (64 + ty*4 + (i - 4));
        const int m = bm*128 + r;
#pragma unroll
        for (int jg = 0; jg < 2; jg++) {
            const int c = bn*128 + (jg ? (64 + tx*4) : (tx*4));
            float4 vv = make_float4(acc[i][jg*4+0], acc[i][jg*4+1],
                                    acc[i][jg*4+2], acc[i][jg*4+3]);
            if (MODE == 0) {
                const int bb_ = m >> 11;
                const int sI  = m & 2047;
                const int hh  = c >> 6;
                const int d   = c & 63;
                *(float4*)&C[(((size_t)hh*Sn + sI)*Bn + bb_)*Dn + d] = vv;
            } else {
                *(float4*)&C[(size_t)m*En + c] = vv;
            }
        }
    }
}

template<int MODE>
__global__ void __launch_bounds__(256, 2) gemm_nt(const float* __restrict__ A,
                                                  const float* __restrict__ Bw,
                                                  float* __restrict__ C)
{
    gemm_body<MODE>(A, Bw, C, blockIdx.y, blockIdx.x);
}

// ---------------------------------------------------------------------------
// Warp-local N-value xor-tree reduction over 32 lanes.
// ---------------------------------------------------------------------------
template<int N>
__device__ __forceinline__ void wredN(float* v)
{
#pragma unroll
    for (int off = 16; off > 0; off >>= 1)
#pragma unroll
        for (int i = 0; i < N; i++)
            v[i] += __shfl_xor_sync(0xffffffffu, v[i], off);
}

// ---------------------------------------------------------------------------
// TTT scan body: one CTA per head, 256 threads = 8 warps.
// warp w: b = w>>1 (batch), half = w&1 (8-row d-slice). lane owns e = {2l,2l+1}.
// All LN/grad reductions are warp-local shfl chains (both halves duplicate).
// 5 __syncthreads per token for cross-batch exchanges.
// ---------------------------------------------------------------------------
__device__ __forceinline__ void scan_body(
    const float* __restrict__ fw_W, const float* __restrict__ fw_b,
    const float* __restrict__ fw_g, const float* __restrict__ fw_bl,
    const float* __restrict__ ttt_g, const float* __restrict__ ttt_b)
{
    const int h = blockIdx.x;
    const int t = threadIdx.x;
    const int w = t >> 5;
    const int b = w >> 1;
    const int half = w & 1;
    const int l = t & 31;
    const int e0 = 2*l;
    const int dbase = b*16 + half*8;

    __shared__ __align__(16) float k_s[4][64];
    __shared__ __align__(16) float part_s[4][8][64];   // [b'][dgrp][e]
    __shared__ __align__(16) float dh1_s[4][64];
    __shared__ __align__(16) float dpv1_s[4][64];
    __shared__ __align__(16) float dph1_s[4][64];
    __shared__ __align__(16) float dh2_s[4][64];
    __shared__ __align__(16) float dpv2_s[4][64];
    __shared__ __align__(16) float dph2_s[4][64];
    __shared__ __align__(16) float dhs_s[4][64];

    float Wr[8][2];
    {
        const float* W0 = fw_W + ((size_t)h*Dn + dbase)*Dn + e0;
#pragma unroll
        for (int i = 0; i < 8; i++) { Wr[i][0] = W0[i*Dn]; Wr[i][1] = W0[i*Dn + 1]; }
    }
    float bp[2], gp[2], blp[2], tgv[2], tbv[2];
#pragma unroll
    for (int j = 0; j < 2; j++) {
        bp[j]  = fw_b [h*Dn + e0 + j];
        gp[j]  = fw_g [h*Dn + e0 + j];
        blp[j] = fw_bl[h*Dn + e0 + j];
        tgv[j] = ttt_g[h*Dn + e0 + j];
        tbv[j] = ttt_b[h*Dn + e0 + j];
    }

    const float* kh = g_k + (size_t)h*Sn*256 + b*64 + e0;
    const float* vh = g_v + (size_t)h*Sn*256 + b*64 + e0;
    const float* qh = g_q + (size_t)h*Sn*256 + b*64 + e0;
    float2 kp = *(const float2*)kh;
    float2 vp = *(const float2*)vh;
    float2 qp = *(const float2*)qh;

    const float LR = 0.1f, EPS = 1e-5f;
    const float C0 = 2.0f/4096.0f, IN = 1.0f/64.0f;

    for (int s = 0; s < Sn; s++) {
        __syncthreads();                                  // S1: prior readers done
        const float kx = kp.x, ky = kp.y;
        const float vx = vp.x, vy = vp.y;
        const float qx = qp.x, qy = qp.y;
        if (half == 0) *(float2*)&k_s[b][e0] = kp;
        if (s + 1 < Sn) {
            kp = *(const float2*)(kh + (size_t)(s+1)*256);
            vp = *(const float2*)(vh + (size_t)(s+1)*256);
            qp = *(const float2*)(qh + (size_t)(s+1)*256);
        }
        __syncthreads();                                  // S2: k_s visible

        // Gram row for own b (reduced later in the r-batch)
        float rr[6];
        rr[2] = kx*k_s[0][e0] + ky*k_s[0][e0+1];
        rr[3] = kx*k_s[1][e0] + ky*k_s[1][e0+1];
        rr[4] = kx*k_s[2][e0] + ky*k_s[2][e0+1];
        rr[5] = kx*k_s[3][e0] + ky*k_s[3][e0+1];

        // forward partials over this thread's 8 d-rows (all 4 batches)
        float pf[4][2];
#pragma unroll
        for (int bb = 0; bb < 4; bb++) { pf[bb][0] = 0.f; pf[bb][1] = 0.f; }
#pragma unroll
        for (int u = 0; u < 2; u++) {
#pragma unroll
            for (int bb = 0; bb < 4; bb++) {
                float4 ka = *(const float4*)&k_s[bb][dbase + 4*u];
                pf[bb][0] += ka.x*Wr[4*u+0][0] + ka.y*Wr[4*u+1][0]
                           + ka.z*Wr[4*u+2][0] + ka.w*Wr[4*u+3][0];
                pf[bb][1] += ka.x*Wr[4*u+0][1] + ka.y*Wr[4*u+1][1]
                           + ka.z*Wr[4*u+2][1] + ka.w*Wr[4*u+3][1];
            }
        }
#pragma unroll
        for (int bb = 0; bb < 4; bb++)
            *(float2*)&part_s[bb][b*2+half][e0] = make_float2(pf[bb][0], pf[bb][1]);
        __syncthreads();                                  // S3: part_s visible

        float h0[2] = {bp[0], bp[1]};
#pragma unroll
        for (int g = 0; g < 8; g++) {
            float2 pv = *(const float2*)&part_s[b][g][e0];
            h0[0] += pv.x; h0[1] += pv.y;
        }
        rr[0] = h0[0] + h0[1];
        rr[1] = h0[0]*h0[0] + h0[1]*h0[1];
        wredN<6>(rr);
        const float mu0 = rr[0]*IN;
        const float rs0 = rsqrtf(rr[1]*IN - mu0*mu0 + EPS);
        const float G0 = rr[2], G1 = rr[3], G2 = rr[4], G3 = rr[5];

        float hat0[2], tgt[2], dp0[2], dhat0[2];
        tgt[0] = vx - kx; tgt[1] = vy - ky;
#pragma unroll
        for (int j = 0; j < 2; j++) {
            hat0[j]  = (h0[j] - mu0)*rs0;
            dp0[j]   = C0*(hat0[j]*gp[j] + blp[j] - tgt[j]);
            dhat0[j] = dp0[j]*gp[j];
        }
        float r2[2] = { dhat0[0]+dhat0[1], dhat0[0]*hat0[0]+dhat0[1]*hat0[1] };
        wredN<2>(r2);
        float dh0[2];
#pragma unroll
        for (int j = 0; j < 2; j++)
            dh0[j] = rs0*(dhat0[j] - r2[0]*IN - hat0[j]*(r2[1]*IN));
        if (half == 0) {
            *(float2*)&dh1_s [b][e0] = make_float2(dh0[0], dh0[1]);
            *(float2*)&dpv1_s[b][e0] = make_float2(dp0[0], dp0[1]);
            *(float2*)&dph1_s[b][e0] = make_float2(dp0[0]*hat0[0], dp0[1]*hat0[1]);
        }
        __syncthreads();                                  // S4: step-1 exchange

        float sdh[2], sdp[2], sdph[2], gd[2];
        {
            float2 a0 = *(const float2*)&dh1_s[0][e0];
            float2 a1 = *(const float2*)&dh1_s[1][e0];
            float2 a2 = *(const float2*)&dh1_s[2][e0];
            float2 a3 = *(const float2*)&dh1_s[3][e0];
            sdh[0] = a0.x+a1.x+a2.x+a3.x;   sdh[1] = a0.y+a1.y+a2.y+a3.y;
            gd[0]  = G0*a0.x+G1*a1.x+G2*a2.x+G3*a3.x;
            gd[1]  = G0*a0.y+G1*a1.y+G2*a2.y+G3*a3.y;
            float2 p0 = *(const float2*)&dpv1_s[0][e0];
            float2 p1 = *(const float2*)&dpv1_s[1][e0];
            float2 p2 = *(const float2*)&dpv1_s[2][e0];
            float2 p3 = *(const float2*)&dpv1_s[3][e0];
            sdp[0] = p0.x+p1.x+p2.x+p3.x;   sdp[1] = p0.y+p1.y+p2.y+p3.y;
            float2 c0 = *(const float2*)&dph1_s[0][e0];
            float2 c1 = *(const float2*)&dph1_s[1][e0];
            float2 c2 = *(const float2*)&dph1_s[2][e0];
            float2 c3 = *(const float2*)&dph1_s[3][e0];
            sdph[0] = c0.x+c1.x+c2.x+c3.x;  sdph[1] = c0.y+c1.y+c2.y+c3.y;
        }
        float g1[2], bl1[2], b1[2], h1[2];
#pragma unroll
        for (int j = 0; j < 2; j++) {
            g1[j]  = gp[j]  - LR*sdph[j];
            bl1[j] = blp[j] - LR*sdp[j];
            b1[j]  = bp[j]  - LR*sdh[j];
            h1[j]  = h0[j]  - LR*(gd[j] + sdh[j]);
        }

        float r3[2] = { h1[0]+h1[1], h1[0]*h1[0]+h1[1]*h1[1] };
        wredN<2>(r3);
        const float mu1 = r3[0]*IN;
        const float rs1 = rsqrtf(r3[1]*IN - mu1*mu1 + EPS);
        float hat1[2], dp1[2], dhat1[2];
#pragma unroll
        for (int j = 0; j < 2; j++) {
            hat1[j]  = (h1[j] - mu1)*rs1;
            dp1[j]   = C0*(hat1[j]*g1[j] + bl1[j] - tgt[j]);
            dhat1[j] = dp1[j]*g1[j];
        }
        float r4[2] = { dhat1[0]+dhat1[1], dhat1[0]*hat1[0]+dhat1[1]*hat1[1] };
        wredN<2>(r4);
        float dh1v[2];
#pragma unroll
        for (int j = 0; j < 2; j++)
            dh1v[j] = rs1*(dhat1[j] - r4[0]*IN - hat1[j]*(r4[1]*IN));
        if (half == 0) {
            *(float2*)&dh2_s [b][e0] = make_float2(dh1v[0], dh1v[1]);
            *(float2*)&dpv2_s[b][e0] = make_float2(dp1[0], dp1[1]);
            *(float2*)&dph2_s[b][e0] = make_float2(dp1[0]*hat1[0], dp1[1]*hat1[1]);
            *(float2*)&dhs_s [b][e0] = make_float2(dh0[0]+dh1v[0], dh0[1]+dh1v[1]);
        }
        __syncthreads();                                  // S5: step-2 exchange

        float sdh1[2], sdp1[2], sdph1[2], gd1[2];
        {
            float2 a0 = *(const float2*)&dh2_s[0][e0];
            float2 a1 = *(const float2*)&dh2_s[1][e0];
            float2 a2 = *(const float2*)&dh2_s[2][e0];
            float2 a3 = *(const float2*)&dh2_s[3][e0];
            sdh1[0] = a0.x+a1.x+a2.x+a3.x;  sdh1[1] = a0.y+a1.y+a2.y+a3.y;
            gd1[0]  = G0*a0.x+G1*a1.x+G2*a2.x+G3*a3.x;
            gd1[1]  = G0*a0.y+G1*a1.y+G2*a2.y+G3*a3.y;
            float2 p0 = *(const float2*)&dpv2_s[0][e0];
            float2 p1 = *(const float2*)&dpv2_s[1][e0];
            float2 p2 = *(const float2*)&dpv2_s[2][e0];
            float2 p3 = *(const float2*)&dpv2_s[3][e0];
            sdp1[0] = p0.x+p1.x+p2.x+p3.x;  sdp1[1] = p0.y+p1.y+p2.y+p3.y;
            float2 c0 = *(const float2*)&dph2_s[0][e0];
            float2 c1 = *(const float2*)&dph2_s[1][e0];
            float2 c2 = *(const float2*)&dph2_s[2][e0];
            float2 c3 = *(const float2*)&dph2_s[3][e0];
            sdph1[0] = c0.x+c1.x+c2.x+c3.x; sdph1[1] = c0.y+c1.y+c2.y+c3.y;
        }
        float g2[2], bl2[2], b2v[2], h2[2];
#pragma unroll
        for (int j = 0; j < 2; j++) {
            g2[j]  = g1[j]  - LR*sdph1[j];
            bl2[j] = bl1[j] - LR*sdp1[j];
            b2v[j] = b1[j]  - LR*sdh1[j];
            h2[j]  = h1[j]  - LR*(gd1[j] + sdh1[j]);
        }

        float r5[2] = { h2[0]+h2[1], h2[0]*h2[0]+h2[1]*h2[1] };
        wredN<2>(r5);
        const float mu2 = r5[0]*IN;
        const float rs2 = rsqrtf(r5[1]*IN - mu2*mu2 + EPS);
        float z[2];
#pragma unroll
        for (int j = 0; j < 2; j++)
            z[j] = (h2[j] - mu2)*rs2*g2[j] + bl2[j];
        float r6[2] = { z[0]+z[1], z[0]*z[0]+z[1]*z[1] };
        wredN<2>(r6);
        const float muz = r6[0]*IN;
        const float rsz = rsqrtf(r6[1]*IN - muz*muz + EPS);
        if (half == 0) {
            float2 o;
            o.x = qx + (z[0] - muz)*rsz*tgv[0] + tbv[0];
            o.y = qy + (z[1] - muz)*rsz*tgv[1] + tbv[1];
            *(float2*)&g_o1[((size_t)(b*Sn + s))*En + h*Dn + e0] = o;
        }
#pragma unroll
        for (int j = 0; j < 2; j++) { gp[j] = g2[j]; blp[j] = bl2[j]; bp[j] = b2v[j]; }

        // W update: W[d][e] -= LR * sum_b' k[b'][d] * (dh0+dh1)[b'][e]
        float2 cb[4];
#pragma unroll
        for (int bb = 0; bb < 4; bb++) {
            float2 dv = *(const float2*)&dhs_s[bb][e0];
            cb[bb].x = LR*dv.x; cb[bb].y = LR*dv.y;
        }
#pragma unroll
        for (int u = 0; u < 2; u++) {
#pragma unroll
            for (int bb = 0; bb < 4; bb++) {
                float4 ka = *(const float4*)&k_s[bb][dbase + 4*u];
                Wr[4*u+0][0] -= ka.x*cb[bb].x;  Wr[4*u+0][1] -= ka.x*cb[bb].y;
                Wr[4*u+1][0] -= ka.y*cb[bb].x;  Wr[4*u+1][1] -= ka.y*cb[bb].y;
                Wr[4*u+2][0] -= ka.z*cb[bb].x;  Wr[4*u+2][1] -= ka.z*cb[bb].y;
                Wr[4*u+3][0] -= ka.w*cb[bb].x;  Wr[4*u+3][1] -= ka.w*cb[bb].y;
            }
        }
    }
}

// ---------------------------------------------------------------------------
// Fat kernel: blocks 0..15 run the scan (16 heads); blocks 16..527 run the
// gate GEMM on the otherwise-idle SMs.
// ---------------------------------------------------------------------------
__global__ void __launch_bounds__(256, 2) scan_plus_gate(
    const float* __restrict__ x, const float* __restrict__ Wg,
    const float* __restrict__ fw_W, const float* __restrict__ fw_b,
    const float* __restrict__ fw_g, const float* __restrict__ fw_bl,
    const float* __restrict__ ttt_g, const float* __restrict__ ttt_b)
{
    if (blockIdx.x >= 16) {
        const int bid = blockIdx.x - 16;
        gemm_body<1>(x, Wg, g_gate, bid >> 3, bid & 7);
        return;
    }
    scan_body(fw_W, fw_b, fw_g, fw_bl, ttt_g, ttt_b);
}

// ---------------------------------------------------------------------------
// Fused post-LayerNorm * gelu(gate), in-place into g_gate.
// ---------------------------------------------------------------------------
__global__ void __launch_bounds__(256, 1) postgate_kernel(
    const float* __restrict__ pg, const float* __restrict__ pb)
{
    const int row = blockIdx.x;
    const int t = threadIdx.x;
    const int w = t >> 5, lane = t & 31;
    const float* xr = g_o1 + (size_t)row*En;

    float v[4];
    float s = 0.f, ss = 0.f;
#pragma unroll
    for (int j = 0; j < 4; j++) {
        float xv = xr[t + 256*j];
        v[j] = xv; s += xv; ss += xv*xv;
    }
#pragma unroll
    for (int off = 16; off > 0; off >>= 1) {
        s  += __shfl_xor_sync(0xffffffffu, s, off);
        ss += __shfl_xor_sync(0xffffffffu, ss, off);
    }
    __shared__ float rsm[16];
    if (lane == 0) { rsm[w] = s; rsm[8 + w] = ss; }
    __syncthreads();
    float S = 0.f, SS = 0.f;
#pragma unroll
    for (int i = 0; i < 8; i++) { S += rsm[i]; SS += rsm[8 + i]; }
    const float mu = S * (1.0f/1024.0f);
    const float r  = rsqrtf(SS * (1.0f/1024.0f) - mu*mu + 1e-5f);

    float* gr = g_gate + (size_t)row*En;
#pragma unroll
    for (int j = 0; j < 4; j++) {
        const int e_ = t + 256*j;
        const float y  = (v[j] - mu)*r*pg[e_] + pb[e_];
        const float xg = gr[e_];
        const float gl = 0.5f*xg*(1.0f + tanhf(0.7978845608028654f*
                                 (xg + 0.044715f*xg*xg*xg)));
        gr[e_] = y * gl;
    }
}

// ---------------------------------------------------------------------------
extern "C" void kernel_launch(void* const* d_in, const int* in_sizes, int n_in,
                              void* d_out, int out_size)
{
    const float* x    = (const float*)d_in[0];
    const float* Wq   = (const float*)d_in[1];
    const float* Wk   = (const float*)d_in[2];
    const float* Wv   = (const float*)d_in[3];
    const float* Wo   = (const float*)d_in[4];
    const float* Wg   = (const float*)d_in[5];
    const float* fwW  = (const float*)d_in[6];
    const float* fwb  = (const float*)d_in[7];
    const float* fwg  = (const float*)d_in[8];
    const float* fwbl = (const float*)d_in[9];
    const float* tttg = (const float*)d_in[10];
    const float* tttb = (const float*)d_in[11];
    const float* pg   = (const float*)d_in[12];
    const float* pb   = (const float*)d_in[13];
    float* out = (float*)d_out;

    float *pq, *pk, *pv, *pgt;
    cudaGetSymbolAddress((void**)&pq,  g_q);
    cudaGetSymbolAddress((void**)&pk,  g_k);
    cudaGetSymbolAddress((void**)&pv,  g_v);
    cudaGetSymbolAddress((void**)&pgt, g_gate);

    dim3 grid(En/128, Mn/128), blk(256);
    gemm_nt<0><<<grid, blk>>>(x, Wq, pq);
    gemm_nt<0><<<grid, blk>>>(x, Wk, pk);
    gemm_nt<0><<<grid, blk>>>(x, Wv, pv);
    scan_plus_gate<<<16 + 512, 256>>>(x, Wg, fwW, fwb, fwg, fwbl, tttg, tttb);
    postgate_kernel<<<Mn, 256>>>(pg, pb);
    gemm_nt<1><<<grid, blk>>>(pgt, Wo, out);
}